// round 14
// baseline (speedup 1.0000x reference)
#include <cuda_runtime.h>
#include <cuda_bf16.h>
#include <math.h>

#define Bb   2
#define Ss   2048
#define Dd   1024
#define Hh   16
#define HDd  64
#define Ff   4096
#define NTOK (Bb*Ss)   // 4096

// ---------------- scratch (device globals) --------------------------------------
__device__ __nv_bfloat16 gb_y[NTOK*Dd];         // LN output (bf16)
__device__ float g_qkv[NTOK*3*Dd];              // fused QKV (fp32, flash input)
__device__ __nv_bfloat16 gb_o[NTOK*Dd];         // attention out (bf16)
__device__ float g_h [NTOK*Dd];                 // residual stream (exact f32)
__device__ __nv_bfloat16 gb_a[NTOK*Dd];         // attn-2 proj out (bf16)
__device__ __nv_bfloat16 gb_t[NTOK*Ff];         // FFN mid (bf16)
// bf16 TRANSPOSED weight copies: W^T[n][k]; qkv concatenated along n
__device__ __nv_bfloat16 gb_wqkv[3*Dd*Dd], gb_wo[Dd*Dd];
__device__ __nv_bfloat16 gb_w1[Ff*Dd], gb_w2[Dd*Ff];

// ---------------- helpers -------------------------------------------------------
__device__ __forceinline__ unsigned f2tf(float x){
    unsigned u; asm("cvt.rna.tf32.f32 %0, %1;" : "=r"(u) : "f"(x)); return u;
}
__device__ __forceinline__ float rndtf(float x){ return __uint_as_float(f2tf(x)); }
__device__ __forceinline__ float geluf(float x){
    return 0.5f * x * (1.0f + erff(x * 0.70710678118654752f));
}
__device__ __forceinline__ void mma8(float* c, const unsigned* a, unsigned b0, unsigned b1){
    asm volatile(
        "mma.sync.aligned.m16n8k8.row.col.f32.tf32.tf32.f32 "
        "{%0,%1,%2,%3}, {%4,%5,%6,%7}, {%8,%9}, {%0,%1,%2,%3};"
        : "+f"(c[0]), "+f"(c[1]), "+f"(c[2]), "+f"(c[3])
        : "r"(a[0]), "r"(a[1]), "r"(a[2]), "r"(a[3]), "r"(b0), "r"(b1));
}
__device__ __forceinline__ void mma16bf(float* c, const unsigned* a, unsigned b0, unsigned b1){
    asm volatile(
        "mma.sync.aligned.m16n8k16.row.col.f32.bf16.bf16.f32 "
        "{%0,%1,%2,%3}, {%4,%5,%6,%7}, {%8,%9}, {%0,%1,%2,%3};"
        : "+f"(c[0]), "+f"(c[1]), "+f"(c[2]), "+f"(c[3])
        : "r"(a[0]), "r"(a[1]), "r"(a[2]), "r"(a[3]), "r"(b0), "r"(b1));
}
__device__ __forceinline__ void cpa16(void* dst, const void* src){
    unsigned d = (unsigned)__cvta_generic_to_shared(dst);
    asm volatile("cp.async.cg.shared.global [%0], [%1], 16;" :: "r"(d), "l"(src));
}
__device__ __forceinline__ void cp_commit(){ asm volatile("cp.async.commit_group;"); }
template<int N> __device__ __forceinline__ void cp_wait(){
    asm volatile("cp.async.wait_group %0;" :: "n"(N));
}

// ---------------- batched weight transpose: 4x (f32 [1024][1024] -> bf16 W^T) ----
__global__ void transpose4_kernel(const float* s0, const float* s1,
                                  const float* s2, const float* s3,
                                  __nv_bfloat16* d0, __nv_bfloat16* d1,
                                  __nv_bfloat16* d2, __nv_bfloat16* d3)
{
    __shared__ float tile[32][33];
    const float* in; __nv_bfloat16* out;
    switch (blockIdx.z){
        case 0: in=s0; out=d0; break;
        case 1: in=s1; out=d1; break;
        case 2: in=s2; out=d2; break;
        default: in=s3; out=d3; break;
    }
    int k0 = blockIdx.y*32, n0 = blockIdx.x*32;
    int tx = threadIdx.x, ty = threadIdx.y;
    #pragma unroll
    for (int j=0;j<4;j++)
        tile[ty+8*j][tx] = in[(size_t)(k0+ty+8*j)*Dd + n0 + tx];
    __syncthreads();
    #pragma unroll
    for (int j=0;j<4;j++)
        out[(size_t)(n0+ty+8*j)*Dd + k0 + tx] = __float2bfloat16_rn(tile[tx][ty+8*j]);
}

// ---------------- generic transpose-convert: f32 [K][N] -> bf16 [N][K] -----------
__global__ void transpose_bf16_kernel(const float* __restrict__ in,
                                      __nv_bfloat16* __restrict__ out,
                                      int K, int N)
{
    __shared__ float tile[32][33];
    int k0 = blockIdx.y*32, n0 = blockIdx.x*32;
    int tx = threadIdx.x, ty = threadIdx.y;
    #pragma unroll
    for (int j=0;j<4;j++)
        tile[ty+8*j][tx] = in[(size_t)(k0+ty+8*j)*N + n0 + tx];
    __syncthreads();
    #pragma unroll
    for (int j=0;j<4;j++)
        out[(size_t)(n0+ty+8*j)*K + k0 + tx] = __float2bfloat16_rn(tile[tx][ty+8*j]);
}

// ---------------- LayerNorm (bf16 output) ---------------------------------------
__global__ void ln_kernel(const float* __restrict__ x,
                          const float* __restrict__ gam,
                          const float* __restrict__ bet,
                          __nv_bfloat16* __restrict__ y)
{
    __shared__ float rs[2][8];
    int row = blockIdx.x, t = threadIdx.x;
    float4 v = ((const float4*)(x + (size_t)row*Dd))[t];
    float s = v.x+v.y+v.z+v.w;
    float q = v.x*v.x+v.y*v.y+v.z*v.z+v.w*v.w;
    #pragma unroll
    for (int o=16;o;o>>=1){ s += __shfl_xor_sync(0xffffffffu,s,o);
                            q += __shfl_xor_sync(0xffffffffu,q,o); }
    if ((t&31)==0){ rs[0][t>>5]=s; rs[1][t>>5]=q; }
    __syncthreads();
    float S=0.f,Q=0.f;
    #pragma unroll
    for (int i=0;i<8;i++){ S+=rs[0][i]; Q+=rs[1][i]; }
    float mu = S*(1.0f/Dd);
    float var = Q*(1.0f/Dd) - mu*mu;
    float rstd = rsqrtf(var + 1e-5f);
    float4 g4 = ((const float4*)gam)[t];
    float4 b4 = ((const float4*)bet)[t];
    __nv_bfloat162 p0, p1;
    p0.x = __float2bfloat16_rn((v.x-mu)*rstd*g4.x + b4.x);
    p0.y = __float2bfloat16_rn((v.y-mu)*rstd*g4.y + b4.y);
    p1.x = __float2bfloat16_rn((v.z-mu)*rstd*g4.z + b4.z);
    p1.y = __float2bfloat16_rn((v.w-mu)*rstd*g4.w + b4.w);
    __nv_bfloat162* yp = (__nv_bfloat162*)(y + (size_t)row*Dd + t*4);
    yp[0] = p0; yp[1] = p1;
}

// ---------------- flash attention (tf32 mma, online softmax, bf16 output) -------
// Q/K/V read from fused buffer with row stride ldx.
#define QS_LD 68
#define VS_LD 72
#define PS_LD 132
#define FLASH_SMEM ((128*QS_LD*2 + 128*VS_LD + 128*PS_LD) * 4)

__global__ __launch_bounds__(256,1)
void flash_kernel(const float* __restrict__ QKV, int ldx,
                  __nv_bfloat16* __restrict__ O)
{
    extern __shared__ float sm[];
    float* Qs = sm;
    float* Ks = Qs + 128*QS_LD;
    float* Vs = Ks + 128*QS_LD;
    float* Ps = Vs + 128*VS_LD;

    int qt = 15 - blockIdx.x;
    int z = blockIdx.y, zb = z >> 4, zh = z & 15;
    const float* Qp = QKV + (size_t)zb*Ss*ldx + zh*HDd;
    const float* Kp = Qp + Dd;
    const float* Vp = Qp + 2*Dd;
    __nv_bfloat16* Op = O + (size_t)zb*Ss*Dd + zh*HDd;

    int tid = threadIdx.x, warp = tid>>5, lane = tid&31;
    int g = lane>>2, tg = lane&3;
    int q0 = qt*128;

    #pragma unroll
    for (int i=0;i<8;i++){
        int idx = tid + i*256;
        int r = idx>>4, c4 = idx&15;
        float4 v4 = *(const float4*)(Qp + (size_t)(q0+r)*ldx + c4*4);
        float4 cv;
        cv.x=rndtf(v4.x); cv.y=rndtf(v4.y); cv.z=rndtf(v4.z); cv.w=rndtf(v4.w);
        *(float4*)&Qs[r*QS_LD + c4*4] = cv;
    }
    __syncthreads();

    unsigned qf[8][4];
    int pr0 = warp*16 + g;
    #pragma unroll
    for (int kc=0;kc<8;kc++){
        qf[kc][0] = __float_as_uint(Qs[ pr0   *QS_LD + kc*8+tg  ]);
        qf[kc][1] = __float_as_uint(Qs[(pr0+8)*QS_LD + kc*8+tg  ]);
        qf[kc][2] = __float_as_uint(Qs[ pr0   *QS_LD + kc*8+tg+4]);
        qf[kc][3] = __float_as_uint(Qs[(pr0+8)*QS_LD + kc*8+tg+4]);
    }

    float oa[8][4];
    #pragma unroll
    for (int i=0;i<8;i++){ oa[i][0]=0.f;oa[i][1]=0.f;oa[i][2]=0.f;oa[i][3]=0.f; }
    float m0=-1e30f, m1=-1e30f, l0=0.f, l1=0.f;
    int grow0 = q0 + pr0, grow1 = grow0 + 8;

    int kt0 = (qt==15) ? 0 : qt;
    for (int kt=kt0; kt<16; kt++){
        __syncthreads();
        #pragma unroll
        for (int i=0;i<8;i++){
            int idx = tid + i*256;
            int r = idx>>4, c4 = idx&15;
            float4 kv = *(const float4*)(Kp + (size_t)(kt*128+r)*ldx + c4*4);
            float4 ck;
            ck.x=rndtf(kv.x); ck.y=rndtf(kv.y); ck.z=rndtf(kv.z); ck.w=rndtf(kv.w);
            *(float4*)&Ks[r*QS_LD + c4*4] = ck;
            float4 vv = *(const float4*)(Vp + (size_t)(kt*128+r)*ldx + c4*4);
            float4 cv;
            cv.x=rndtf(vv.x); cv.y=rndtf(vv.y); cv.z=rndtf(vv.z); cv.w=rndtf(vv.w);
            *(float4*)&Vs[r*VS_LD + c4*4] = cv;
        }
        __syncthreads();

        float sc[16][4];
        #pragma unroll
        for (int nt=0;nt<16;nt++){ sc[nt][0]=0.f;sc[nt][1]=0.f;sc[nt][2]=0.f;sc[nt][3]=0.f; }
        #pragma unroll
        for (int kc=0;kc<8;kc++){
            #pragma unroll
            for (int nt=0;nt<16;nt++){
                unsigned b0 = __float_as_uint(Ks[(nt*8+g)*QS_LD + kc*8+tg  ]);
                unsigned b1 = __float_as_uint(Ks[(nt*8+g)*QS_LD + kc*8+tg+4]);
                mma8(sc[nt], qf[kc], b0, b1);
            }
        }

        float tm0=-1e30f, tm1=-1e30f;
        #pragma unroll
        for (int nt=0;nt<16;nt++){
            #pragma unroll
            for (int j=0;j<4;j++){
                int gcol = kt*128 + nt*8 + tg*2 + (j&1);
                int grow = (j<2) ? grow0 : grow1;
                float s = (gcol<=grow) ? -1e9f : sc[nt][j]*0.125f;
                sc[nt][j] = s;
                if (j<2) tm0 = fmaxf(tm0,s); else tm1 = fmaxf(tm1,s);
            }
        }
        tm0 = fmaxf(tm0, __shfl_xor_sync(0xffffffffu,tm0,1));
        tm0 = fmaxf(tm0, __shfl_xor_sync(0xffffffffu,tm0,2));
        tm1 = fmaxf(tm1, __shfl_xor_sync(0xffffffffu,tm1,1));
        tm1 = fmaxf(tm1, __shfl_xor_sync(0xffffffffu,tm1,2));
        float mn0 = fmaxf(m0,tm0), mn1 = fmaxf(m1,tm1);
        float sf0 = __expf(m0-mn0), sf1 = __expf(m1-mn1);
        float rs0=0.f, rs1=0.f;
        #pragma unroll
        for (int nt=0;nt<16;nt++){
            sc[nt][0] = __expf(sc[nt][0]-mn0); rs0 += sc[nt][0];
            sc[nt][1] = __expf(sc[nt][1]-mn0); rs0 += sc[nt][1];
            sc[nt][2] = __expf(sc[nt][2]-mn1); rs1 += sc[nt][2];
            sc[nt][3] = __expf(sc[nt][3]-mn1); rs1 += sc[nt][3];
        }
        rs0 += __shfl_xor_sync(0xffffffffu,rs0,1);
        rs0 += __shfl_xor_sync(0xffffffffu,rs0,2);
        rs1 += __shfl_xor_sync(0xffffffffu,rs1,1);
        rs1 += __shfl_xor_sync(0xffffffffu,rs1,2);
        l0 = l0*sf0 + rs0;  l1 = l1*sf1 + rs1;
        m0 = mn0;  m1 = mn1;
        #pragma unroll
        for (int i=0;i<8;i++){
            oa[i][0]*=sf0; oa[i][1]*=sf0; oa[i][2]*=sf1; oa[i][3]*=sf1;
        }

        #pragma unroll
        for (int nt=0;nt<16;nt++){
            float2 pa, pb;
            pa.x = rndtf(sc[nt][0]); pa.y = rndtf(sc[nt][1]);
            pb.x = rndtf(sc[nt][2]); pb.y = rndtf(sc[nt][3]);
            *(float2*)&Ps[ pr0   *PS_LD + nt*8 + tg*2] = pa;
            *(float2*)&Ps[(pr0+8)*PS_LD + nt*8 + tg*2] = pb;
        }
        __syncwarp();
        #pragma unroll
        for (int kc2=0;kc2<16;kc2++){
            unsigned pf[4];
            pf[0] = __float_as_uint(Ps[ pr0   *PS_LD + kc2*8+tg  ]);
            pf[1] = __float_as_uint(Ps[(pr0+8)*PS_LD + kc2*8+tg  ]);
            pf[2] = __float_as_uint(Ps[ pr0   *PS_LD + kc2*8+tg+4]);
            pf[3] = __float_as_uint(Ps[(pr0+8)*PS_LD + kc2*8+tg+4]);
            #pragma unroll
            for (int nt2=0;nt2<8;nt2++){
                unsigned b0 = __float_as_uint(Vs[(kc2*8+tg  )*VS_LD + nt2*8+g]);
                unsigned b1 = __float_as_uint(Vs[(kc2*8+tg+4)*VS_LD + nt2*8+g]);
                mma8(oa[nt2], pf, b0, b1);
            }
        }
    }

    float inv0 = 1.f/l0, inv1 = 1.f/l1;
    #pragma unroll
    for (int nt2=0;nt2<8;nt2++){
        __nv_bfloat162 w0, w1;
        w0.x = __float2bfloat16_rn(oa[nt2][0]*inv0);
        w0.y = __float2bfloat16_rn(oa[nt2][1]*inv0);
        w1.x = __float2bfloat16_rn(oa[nt2][2]*inv1);
        w1.y = __float2bfloat16_rn(oa[nt2][3]*inv1);
        *(__nv_bfloat162*)(Op + (size_t)grow0*Dd + nt2*8 + tg*2) = w0;
        *(__nv_bfloat162*)(Op + (size_t)grow1*Dd + nt2*8 + tg*2) = w1;
    }
}

// ---------------- pipelined bf16 GEMM (round-8 proven mainloop) ------------------
// C[M,N] = A[M,K](bf16) @ B[K,N], B given TRANSPOSED bf16 BT[n][k].
// mma.sync.m16n8k16 bf16, fp32 accum. SMEM stride 72 halfs (36 words = 4 mod 32):
// all fragment LDS.32 conflict-free.
#define BKg  64
#define ALD  72                       // halfs per smem row
#define ASTG (128*ALD)                // halfs per stage (A and B identical)
#define GEMM_SMEM (4*ASTG*2)          // 73728 bytes

template<bool DO_GELU, bool OUT_BF16>
__global__ __launch_bounds__(256,2)
void gemm_bf16(const __nv_bfloat16* __restrict__ A, int lda,
               const __nv_bfloat16* __restrict__ BT, int ldb,
               void* __restrict__ Cv, int ldc,
               int M, int N, int K,
               const float* __restrict__ bias,
               const float* __restrict__ Rm, int ldr)
{
    constexpr int MT = 4, NTn = 4;            // 64x32 warp tile
    extern __shared__ __nv_bfloat16 hsm[];

    int m0 = blockIdx.y*128, n0 = blockIdx.x*128;
    int tid = threadIdx.x, warp = tid>>5, lane = tid&31;
    int wm = (warp>>2)*64, wn = (warp&3)*32;
    int g = lane>>2, tg = lane&3;

    int cr = tid>>3, cch = (tid&7)*8;         // copy: row base, col offset (halfs)
    const __nv_bfloat16* Ap = A  + (size_t)(m0+cr)*lda + cch;
    const __nv_bfloat16* Bp = BT + (size_t)(n0+cr)*ldb + cch;

    float acc[MT][NTn][4];
    #pragma unroll
    for (int i=0;i<MT;i++)
        #pragma unroll
        for (int j=0;j<NTn;j++)
            #pragma unroll
            for (int r=0;r<4;r++) acc[i][j][r]=0.f;

    auto issue = [&](int k0, int s){
        __nv_bfloat16* As = hsm + s*ASTG;
        __nv_bfloat16* Bs = hsm + 2*ASTG + s*ASTG;
        #pragma unroll
        for (int i=0;i<4;i++)
            cpa16(&As[(cr+32*i)*ALD + cch], Ap + (size_t)(32*i)*lda + k0);
        #pragma unroll
        for (int i=0;i<4;i++)
            cpa16(&Bs[(cr+32*i)*ALD + cch], Bp + (size_t)(32*i)*ldb + k0);
        cp_commit();
    };

    int nk = K/BKg;
    issue(0, 0);
    for (int it=0; it<nk; it++){
        int s = it&1;
        if (it+1 < nk) issue((it+1)*BKg, s^1);
        if (it+1 < nk) cp_wait<1>(); else cp_wait<0>();
        __syncthreads();

        const __nv_bfloat16* As = hsm + s*ASTG;
        const __nv_bfloat16* Bs = hsm + 2*ASTG + s*ASTG;
        #pragma unroll
        for (int ks=0; ks<BKg/16; ks++){
            int kk = ks*16 + 2*tg;
            unsigned af[MT][4], bf[NTn][2];
            #pragma unroll
            for (int mt=0; mt<MT; mt++){
                const __nv_bfloat16* ap = As + (wm + mt*16 + g)*ALD + kk;
                af[mt][0] = *(const unsigned*)(ap);
                af[mt][1] = *(const unsigned*)(ap + 8*ALD);
                af[mt][2] = *(const unsigned*)(ap + 8);
                af[mt][3] = *(const unsigned*)(ap + 8*ALD + 8);
            }
            #pragma unroll
            for (int nt=0; nt<NTn; nt++){
                const __nv_bfloat16* bp = Bs + (wn + nt*8 + g)*ALD + kk;
                bf[nt][0] = *(const unsigned*)(bp);
                bf[nt][1] = *(const unsigned*)(bp + 8);
            }
            #pragma unroll
            for (int mt=0; mt<MT; mt++)
                #pragma unroll
                for (int nt=0; nt<NTn; nt++)
                    mma16bf(acc[mt][nt], af[mt], bf[nt][0], bf[nt][1]);
        }
        __syncthreads();
    }

    #pragma unroll
    for (int mt=0; mt<MT; mt++){
        #pragma unroll
        for (int i=0; i<2; i++){
            int row = m0 + wm + mt*16 + g + i*8;
            #pragma unroll
            for (int nt=0; nt<NTn; nt++){
                int col = n0 + wn + nt*8 + tg*2;
                float v0 = acc[mt][nt][i*2+0];
                float v1 = acc[mt][nt][i*2+1];
                if (bias){ v0 += bias[col]; v1 += bias[col+1]; }
                if (DO_GELU){ v0 = geluf(v0); v1 = geluf(v1); }
                if (Rm){
                    float2 rr = *(const float2*)(Rm + (size_t)row*ldr + col);
                    v0 += rr.x; v1 += rr.y;
                }
                if (OUT_BF16){
                    __nv_bfloat162 w;
                    w.x = __float2bfloat16_rn(v0);
                    w.y = __float2bfloat16_rn(v1);
                    *(__nv_bfloat162*)((__nv_bfloat16*)Cv + (size_t)row*ldc + col) = w;
                }else{
                    *(float2*)((float*)Cv + (size_t)row*ldc + col) = make_float2(v0, v1);
                }
            }
        }
    }
}

// ---------------- host-side launch helper ---------------------------------------
enum GMode { G_F32, G_BF16, G_GELU_BF16 };
static void gemm_run(const __nv_bfloat16*A,int lda, const __nv_bfloat16*BT,int ldb,
                     void*C,int ldc, int M,int N,int K,
                     const float*bias,const float*R,int ldr, GMode mode)
{
    dim3 gr(N/128, M/128, 1);
    switch (mode){
    case G_F32:
        gemm_bf16<false,false><<<gr,256,GEMM_SMEM>>>(A,lda,BT,ldb,C,ldc,M,N,K,bias,R,ldr); break;
    case G_BF16:
        gemm_bf16<false,true ><<<gr,256,GEMM_SMEM>>>(A,lda,BT,ldb,C,ldc,M,N,K,bias,R,ldr); break;
    case G_GELU_BF16:
        gemm_bf16<true ,true ><<<gr,256,GEMM_SMEM>>>(A,lda,BT,ldb,C,ldc,M,N,K,bias,R,ldr); break;
    }
}

extern "C" void kernel_launch(void* const* d_in, const int* in_sizes, int n_in,
                              void* d_out, int out_size)
{
    (void)in_sizes; (void)n_in; (void)out_size;
    const float* x   = (const float*)d_in[0];
    const float* wq  = (const float*)d_in[1];
    const float* wk  = (const float*)d_in[2];
    const float* wv  = (const float*)d_in[3];
    const float* wo  = (const float*)d_in[4];
    const float* bo  = (const float*)d_in[5];
    const float* l1g = (const float*)d_in[6];
    const float* l1b = (const float*)d_in[7];
    const float* l2g = (const float*)d_in[8];
    const float* l2b = (const float*)d_in[9];
    const float* w1  = (const float*)d_in[10];
    const float* b1  = (const float*)d_in[11];
    const float* w2  = (const float*)d_in[12];
    const float* b2  = (const float*)d_in[13];
    float* out = (float*)d_out;

    void* p;
    __nv_bfloat16 *y,*o,*a,*tmid,*twqkv,*two,*tw1,*tw2;
    float *qkv,*h;
    cudaGetSymbolAddress(&p, gb_y  ); y     = (__nv_bfloat16*)p;
    cudaGetSymbolAddress(&p, g_qkv ); qkv   = (float*)p;
    cudaGetSymbolAddress(&p, gb_o  ); o     = (__nv_bfloat16*)p;
    cudaGetSymbolAddress(&p, g_h   ); h     = (float*)p;
    cudaGetSymbolAddress(&p, gb_a  ); a     = (__nv_bfloat16*)p;
    cudaGetSymbolAddress(&p, gb_t  ); tmid  = (__nv_bfloat16*)p;
    cudaGetSymbolAddress(&p, gb_wqkv); twqkv = (__nv_bfloat16*)p;
    cudaGetSymbolAddress(&p, gb_wo ); two   = (__nv_bfloat16*)p;
    cudaGetSymbolAddress(&p, gb_w1 ); tw1   = (__nv_bfloat16*)p;
    cudaGetSymbolAddress(&p, gb_w2 ); tw2   = (__nv_bfloat16*)p;

    cudaFuncSetAttribute((const void*)flash_kernel,
                         cudaFuncAttributeMaxDynamicSharedMemorySize, FLASH_SMEM);
    cudaFuncSetAttribute((const void*)gemm_bf16<false,false>,
                         cudaFuncAttributeMaxDynamicSharedMemorySize, GEMM_SMEM);
    cudaFuncSetAttribute((const void*)gemm_bf16<false,true>,
                         cudaFuncAttributeMaxDynamicSharedMemorySize, GEMM_SMEM);
    cudaFuncSetAttribute((const void*)gemm_bf16<true,true>,
                         cudaFuncAttributeMaxDynamicSharedMemorySize, GEMM_SMEM);

    // weights -> transposed bf16 copies (W^T[n][k]); q,k,v concatenated along n
    {
        dim3 tb(32,8);
        transpose4_kernel<<<dim3(Dd/32,Dd/32,4),tb>>>(
            wq, wk, wv, wo,
            twqkv, twqkv + Dd*Dd, twqkv + 2*Dd*Dd, two);
        transpose_bf16_kernel<<<dim3(Ff/32,Dd/32),tb>>>(w1, tw1, Dd, Ff);
        transpose_bf16_kernel<<<dim3(Dd/32,Ff/32),tb>>>(w2, tw2, Ff, Dd);
    }

    for (int pass=0; pass<2; pass++){
        const float* lnin = pass ? h   : x;
        const float* gg   = pass ? l2g : l1g;
        const float* bbv  = pass ? l2b : l1b;
        ln_kernel<<<NTOK,256>>>(lnin, gg, bbv, y);
        // fused QKV projection: [4096,1024] @ [1024,3072] -> [4096,3072]
        gemm_run(y,Dd, twqkv,Dd, qkv,3*Dd, NTOK,3*Dd,Dd, nullptr,nullptr,0, G_F32);
        flash_kernel<<<dim3(16,32),256,FLASH_SMEM>>>(qkv, 3*Dd, o);
        if (pass == 0)
            gemm_run(o,Dd, two,Dd, h,Dd, NTOK,Dd,Dd, bo, x, Dd, G_F32);
        else
            gemm_run(o,Dd, two,Dd, a,Dd, NTOK,Dd,Dd, bo, nullptr,0, G_BF16);
    }
    // FFN: t = gelu(a@w1 + b1) [bf16];  out = t@w2 + b2 + h  [f32]
    gemm_run(a   ,Dd, tw1,Dd, tmid,Ff, NTOK,Ff,Dd, b1, nullptr,0, G_GELU_BF16);
    gemm_run(tmid,Ff, tw2,Ff, out ,Dd, NTOK,Dd,Ff, b2, h, Dd,     G_F32);
}

// round 15
// speedup vs baseline: 1.6224x; 1.6224x over previous
#include <cuda_runtime.h>
#include <cuda_bf16.h>
#include <math.h>

#define Bb   2
#define Ss   2048
#define Dd   1024
#define Hh   16
#define HDd  64
#define Ff   4096
#define NTOK (Bb*Ss)   // 4096

// ---------------- scratch (device globals) --------------------------------------
__device__ __nv_bfloat16 gb_y[NTOK*Dd];         // LN output (bf16)
__device__ float g_q [NTOK*Dd];                 // fp32 (flash inputs)
__device__ float g_k [NTOK*Dd];
__device__ float g_v [NTOK*Dd];
__device__ __nv_bfloat16 gb_o[NTOK*Dd];         // attention out (bf16)
__device__ float g_h [NTOK*Dd];                 // residual stream (exact f32)
__device__ __nv_bfloat16 gb_a[NTOK*Dd];         // attn-2 proj out (bf16)
__device__ __nv_bfloat16 gb_t[NTOK*Ff];         // FFN mid (bf16)
// bf16 TRANSPOSED weight copies: W^T[n][k]
__device__ __nv_bfloat16 gb_wq[Dd*Dd], gb_wk[Dd*Dd], gb_wv[Dd*Dd], gb_wo[Dd*Dd];
__device__ __nv_bfloat16 gb_w1[Ff*Dd], gb_w2[Dd*Ff];

// ---------------- helpers -------------------------------------------------------
__device__ __forceinline__ unsigned f2tf(float x){
    unsigned u; asm("cvt.rna.tf32.f32 %0, %1;" : "=r"(u) : "f"(x)); return u;
}
__device__ __forceinline__ float rndtf(float x){ return __uint_as_float(f2tf(x)); }
__device__ __forceinline__ float geluf(float x){
    return 0.5f * x * (1.0f + erff(x * 0.70710678118654752f));
}
__device__ __forceinline__ void mma8(float* c, const unsigned* a, unsigned b0, unsigned b1){
    asm volatile(
        "mma.sync.aligned.m16n8k8.row.col.f32.tf32.tf32.f32 "
        "{%0,%1,%2,%3}, {%4,%5,%6,%7}, {%8,%9}, {%0,%1,%2,%3};"
        : "+f"(c[0]), "+f"(c[1]), "+f"(c[2]), "+f"(c[3])
        : "r"(a[0]), "r"(a[1]), "r"(a[2]), "r"(a[3]), "r"(b0), "r"(b1));
}
__device__ __forceinline__ void mma16bf(float* c, const unsigned* a, unsigned b0, unsigned b1){
    asm volatile(
        "mma.sync.aligned.m16n8k16.row.col.f32.bf16.bf16.f32 "
        "{%0,%1,%2,%3}, {%4,%5,%6,%7}, {%8,%9}, {%0,%1,%2,%3};"
        : "+f"(c[0]), "+f"(c[1]), "+f"(c[2]), "+f"(c[3])
        : "r"(a[0]), "r"(a[1]), "r"(a[2]), "r"(a[3]), "r"(b0), "r"(b1));
}
__device__ __forceinline__ void ldsm4(unsigned* r, unsigned saddr){
    asm volatile("ldmatrix.sync.aligned.m8n8.x4.shared.b16 {%0,%1,%2,%3}, [%4];"
        : "=r"(r[0]), "=r"(r[1]), "=r"(r[2]), "=r"(r[3]) : "r"(saddr));
}
__device__ __forceinline__ void cpa16(void* dst, const void* src){
    unsigned d = (unsigned)__cvta_generic_to_shared(dst);
    asm volatile("cp.async.cg.shared.global [%0], [%1], 16;" :: "r"(d), "l"(src));
}
__device__ __forceinline__ void cp_commit(){ asm volatile("cp.async.commit_group;"); }
template<int N> __device__ __forceinline__ void cp_wait(){
    asm volatile("cp.async.wait_group %0;" :: "n"(N));
}

// ---------------- batched weight transpose: 4x (f32 [1024][1024] -> bf16 W^T) ----
__global__ void transpose4_kernel(const float* s0, const float* s1,
                                  const float* s2, const float* s3,
                                  __nv_bfloat16* d0, __nv_bfloat16* d1,
                                  __nv_bfloat16* d2, __nv_bfloat16* d3)
{
    __shared__ float tile[32][33];
    const float* in; __nv_bfloat16* out;
    switch (blockIdx.z){
        case 0: in=s0; out=d0; break;
        case 1: in=s1; out=d1; break;
        case 2: in=s2; out=d2; break;
        default: in=s3; out=d3; break;
    }
    int k0 = blockIdx.y*32, n0 = blockIdx.x*32;
    int tx = threadIdx.x, ty = threadIdx.y;
    #pragma unroll
    for (int j=0;j<4;j++)
        tile[ty+8*j][tx] = in[(size_t)(k0+ty+8*j)*Dd + n0 + tx];
    __syncthreads();
    #pragma unroll
    for (int j=0;j<4;j++)
        out[(size_t)(n0+ty+8*j)*Dd + k0 + tx] = __float2bfloat16_rn(tile[tx][ty+8*j]);
}

// ---------------- generic transpose-convert: f32 [K][N] -> bf16 [N][K] -----------
__global__ void transpose_bf16_kernel(const float* __restrict__ in,
                                      __nv_bfloat16* __restrict__ out,
                                      int K, int N)
{
    __shared__ float tile[32][33];
    int k0 = blockIdx.y*32, n0 = blockIdx.x*32;
    int tx = threadIdx.x, ty = threadIdx.y;
    #pragma unroll
    for (int j=0;j<4;j++)
        tile[ty+8*j][tx] = in[(size_t)(k0+ty+8*j)*N + n0 + tx];
    __syncthreads();
    #pragma unroll
    for (int j=0;j<4;j++)
        out[(size_t)(n0+ty+8*j)*K + k0 + tx] = __float2bfloat16_rn(tile[tx][ty+8*j]);
}

// ---------------- LayerNorm (bf16 output) ---------------------------------------
__global__ void ln_kernel(const float* __restrict__ x,
                          const float* __restrict__ gam,
                          const float* __restrict__ bet,
                          __nv_bfloat16* __restrict__ y)
{
    __shared__ float rs[2][8];
    int row = blockIdx.x, t = threadIdx.x;
    float4 v = ((const float4*)(x + (size_t)row*Dd))[t];
    float s = v.x+v.y+v.z+v.w;
    float q = v.x*v.x+v.y*v.y+v.z*v.z+v.w*v.w;
    #pragma unroll
    for (int o=16;o;o>>=1){ s += __shfl_xor_sync(0xffffffffu,s,o);
                            q += __shfl_xor_sync(0xffffffffu,q,o); }
    if ((t&31)==0){ rs[0][t>>5]=s; rs[1][t>>5]=q; }
    __syncthreads();
    float S=0.f,Q=0.f;
    #pragma unroll
    for (int i=0;i<8;i++){ S+=rs[0][i]; Q+=rs[1][i]; }
    float mu = S*(1.0f/Dd);
    float var = Q*(1.0f/Dd) - mu*mu;
    float rstd = rsqrtf(var + 1e-5f);
    float4 g4 = ((const float4*)gam)[t];
    float4 b4 = ((const float4*)bet)[t];
    __nv_bfloat162 p0, p1;
    p0.x = __float2bfloat16_rn((v.x-mu)*rstd*g4.x + b4.x);
    p0.y = __float2bfloat16_rn((v.y-mu)*rstd*g4.y + b4.y);
    p1.x = __float2bfloat16_rn((v.z-mu)*rstd*g4.z + b4.z);
    p1.y = __float2bfloat16_rn((v.w-mu)*rstd*g4.w + b4.w);
    __nv_bfloat162* yp = (__nv_bfloat162*)(y + (size_t)row*Dd + t*4);
    yp[0] = p0; yp[1] = p1;
}

// ---------------- flash attention (round-8 proven: tf32 mma, bf16 output) -------
#define QS_LD 68
#define VS_LD 72
#define PS_LD 132
#define FLASH_SMEM ((128*QS_LD*2 + 128*VS_LD + 128*PS_LD) * 4)

__global__ __launch_bounds__(256,1)
void flash_kernel(const float* __restrict__ Q, const float* __restrict__ K,
                  const float* __restrict__ V, __nv_bfloat16* __restrict__ O)
{
    extern __shared__ float sm[];
    float* Qs = sm;
    float* Ks = Qs + 128*QS_LD;
    float* Vs = Ks + 128*QS_LD;
    float* Ps = Vs + 128*VS_LD;

    int qt = 15 - blockIdx.x;
    int z = blockIdx.y, zb = z >> 4, zh = z & 15;
    const float* Qp = Q + (size_t)zb*Ss*Dd + zh*HDd;
    const float* Kp = K + (size_t)zb*Ss*Dd + zh*HDd;
    const float* Vp = V + (size_t)zb*Ss*Dd + zh*HDd;
    __nv_bfloat16* Op = O + (size_t)zb*Ss*Dd + zh*HDd;

    int tid = threadIdx.x, warp = tid>>5, lane = tid&31;
    int g = lane>>2, tg = lane&3;
    int q0 = qt*128;

    #pragma unroll
    for (int i=0;i<8;i++){
        int idx = tid + i*256;
        int r = idx>>4, c4 = idx&15;
        float4 v4 = *(const float4*)(Qp + (size_t)(q0+r)*Dd + c4*4);
        float4 cv;
        cv.x=rndtf(v4.x); cv.y=rndtf(v4.y); cv.z=rndtf(v4.z); cv.w=rndtf(v4.w);
        *(float4*)&Qs[r*QS_LD + c4*4] = cv;
    }
    __syncthreads();

    unsigned qf[8][4];
    int pr0 = warp*16 + g;
    #pragma unroll
    for (int kc=0;kc<8;kc++){
        qf[kc][0] = __float_as_uint(Qs[ pr0   *QS_LD + kc*8+tg  ]);
        qf[kc][1] = __float_as_uint(Qs[(pr0+8)*QS_LD + kc*8+tg  ]);
        qf[kc][2] = __float_as_uint(Qs[ pr0   *QS_LD + kc*8+tg+4]);
        qf[kc][3] = __float_as_uint(Qs[(pr0+8)*QS_LD + kc*8+tg+4]);
    }

    float oa[8][4];
    #pragma unroll
    for (int i=0;i<8;i++){ oa[i][0]=0.f;oa[i][1]=0.f;oa[i][2]=0.f;oa[i][3]=0.f; }
    float m0=-1e30f, m1=-1e30f, l0=0.f, l1=0.f;
    int grow0 = q0 + pr0, grow1 = grow0 + 8;

    int kt0 = (qt==15) ? 0 : qt;
    for (int kt=kt0; kt<16; kt++){
        __syncthreads();
        #pragma unroll
        for (int i=0;i<8;i++){
            int idx = tid + i*256;
            int r = idx>>4, c4 = idx&15;
            float4 kv = *(const float4*)(Kp + (size_t)(kt*128+r)*Dd + c4*4);
            float4 ck;
            ck.x=rndtf(kv.x); ck.y=rndtf(kv.y); ck.z=rndtf(kv.z); ck.w=rndtf(kv.w);
            *(float4*)&Ks[r*QS_LD + c4*4] = ck;
            float4 vv = *(const float4*)(Vp + (size_t)(kt*128+r)*Dd + c4*4);
            float4 cv;
            cv.x=rndtf(vv.x); cv.y=rndtf(vv.y); cv.z=rndtf(vv.z); cv.w=rndtf(vv.w);
            *(float4*)&Vs[r*VS_LD + c4*4] = cv;
        }
        __syncthreads();

        float sc[16][4];
        #pragma unroll
        for (int nt=0;nt<16;nt++){ sc[nt][0]=0.f;sc[nt][1]=0.f;sc[nt][2]=0.f;sc[nt][3]=0.f; }
        #pragma unroll
        for (int kc=0;kc<8;kc++){
            #pragma unroll
            for (int nt=0;nt<16;nt++){
                unsigned b0 = __float_as_uint(Ks[(nt*8+g)*QS_LD + kc*8+tg  ]);
                unsigned b1 = __float_as_uint(Ks[(nt*8+g)*QS_LD + kc*8+tg+4]);
                mma8(sc[nt], qf[kc], b0, b1);
            }
        }

        float tm0=-1e30f, tm1=-1e30f;
        #pragma unroll
        for (int nt=0;nt<16;nt++){
            #pragma unroll
            for (int j=0;j<4;j++){
                int gcol = kt*128 + nt*8 + tg*2 + (j&1);
                int grow = (j<2) ? grow0 : grow1;
                float s = (gcol<=grow) ? -1e9f : sc[nt][j]*0.125f;
                sc[nt][j] = s;
                if (j<2) tm0 = fmaxf(tm0,s); else tm1 = fmaxf(tm1,s);
            }
        }
        tm0 = fmaxf(tm0, __shfl_xor_sync(0xffffffffu,tm0,1));
        tm0 = fmaxf(tm0, __shfl_xor_sync(0xffffffffu,tm0,2));
        tm1 = fmaxf(tm1, __shfl_xor_sync(0xffffffffu,tm1,1));
        tm1 = fmaxf(tm1, __shfl_xor_sync(0xffffffffu,tm1,2));
        float mn0 = fmaxf(m0,tm0), mn1 = fmaxf(m1,tm1);
        float sf0 = __expf(m0-mn0), sf1 = __expf(m1-mn1);
        float rs0=0.f, rs1=0.f;
        #pragma unroll
        for (int nt=0;nt<16;nt++){
            sc[nt][0] = __expf(sc[nt][0]-mn0); rs0 += sc[nt][0];
            sc[nt][1] = __expf(sc[nt][1]-mn0); rs0 += sc[nt][1];
            sc[nt][2] = __expf(sc[nt][2]-mn1); rs1 += sc[nt][2];
            sc[nt][3] = __expf(sc[nt][3]-mn1); rs1 += sc[nt][3];
        }
        rs0 += __shfl_xor_sync(0xffffffffu,rs0,1);
        rs0 += __shfl_xor_sync(0xffffffffu,rs0,2);
        rs1 += __shfl_xor_sync(0xffffffffu,rs1,1);
        rs1 += __shfl_xor_sync(0xffffffffu,rs1,2);
        l0 = l0*sf0 + rs0;  l1 = l1*sf1 + rs1;
        m0 = mn0;  m1 = mn1;
        #pragma unroll
        for (int i=0;i<8;i++){
            oa[i][0]*=sf0; oa[i][1]*=sf0; oa[i][2]*=sf1; oa[i][3]*=sf1;
        }

        #pragma unroll
        for (int nt=0;nt<16;nt++){
            float2 pa, pb;
            pa.x = rndtf(sc[nt][0]); pa.y = rndtf(sc[nt][1]);
            pb.x = rndtf(sc[nt][2]); pb.y = rndtf(sc[nt][3]);
            *(float2*)&Ps[ pr0   *PS_LD + nt*8 + tg*2] = pa;
            *(float2*)&Ps[(pr0+8)*PS_LD + nt*8 + tg*2] = pb;
        }
        __syncwarp();
        #pragma unroll
        for (int kc2=0;kc2<16;kc2++){
            unsigned pf[4];
            pf[0] = __float_as_uint(Ps[ pr0   *PS_LD + kc2*8+tg  ]);
            pf[1] = __float_as_uint(Ps[(pr0+8)*PS_LD + kc2*8+tg  ]);
            pf[2] = __float_as_uint(Ps[ pr0   *PS_LD + kc2*8+tg+4]);
            pf[3] = __float_as_uint(Ps[(pr0+8)*PS_LD + kc2*8+tg+4]);
            #pragma unroll
            for (int nt2=0;nt2<8;nt2++){
                unsigned b0 = __float_as_uint(Vs[(kc2*8+tg  )*VS_LD + nt2*8+g]);
                unsigned b1 = __float_as_uint(Vs[(kc2*8+tg+4)*VS_LD + nt2*8+g]);
                mma8(oa[nt2], pf, b0, b1);
            }
        }
    }

    float inv0 = 1.f/l0, inv1 = 1.f/l1;
    #pragma unroll
    for (int nt2=0;nt2<8;nt2++){
        __nv_bfloat162 w0, w1;
        w0.x = __float2bfloat16_rn(oa[nt2][0]*inv0);
        w0.y = __float2bfloat16_rn(oa[nt2][1]*inv0);
        w1.x = __float2bfloat16_rn(oa[nt2][2]*inv1);
        w1.y = __float2bfloat16_rn(oa[nt2][3]*inv1);
        *(__nv_bfloat162*)(Op + (size_t)grow0*Dd + nt2*8 + tg*2) = w0;
        *(__nv_bfloat162*)(Op + (size_t)grow1*Dd + nt2*8 + tg*2) = w1;
    }
}

// ---------------- pipelined bf16 GEMM (cp.async + ldmatrix, r12-verified) --------
// C[M,N] = A[M,K](bf16) @ B[K,N], B given TRANSPOSED bf16 BT[n][k].
// Fragments via ldmatrix.x4 (6 LDSM per k16-step/warp instead of 24 LDS.32);
// mapping numerically verified in round 12 (rel_err bit-identical to LDS path).
// ALD=72 halfs = 144B row stride: ldmatrix phase rows hit banks r*9%8=r%8 -> CF.
#define BKg  64
#define ALD  72                       // halfs per smem row
#define ASTG (128*ALD)                // halfs per stage (A and B identical)
#define GEMM_SMEM (4*ASTG*2)          // 73728 bytes

template<bool DO_GELU, bool OUT_BF16>
__global__ __launch_bounds__(256,2)
void gemm_bf16(const __nv_bfloat16* __restrict__ A, int lda,
               const __nv_bfloat16* __restrict__ BT, int ldb,
               void* __restrict__ Cv, int ldc,
               int M, int N, int K,
               const float* __restrict__ bias,
               const float* __restrict__ Rm, int ldr)
{
    constexpr int MT = 4, NTn = 4;            // 64x32 warp tile
    extern __shared__ __nv_bfloat16 hsm[];
    unsigned hbase = (unsigned)__cvta_generic_to_shared(hsm);

    int m0 = blockIdx.y*128, n0 = blockIdx.x*128;
    int tid = threadIdx.x, warp = tid>>5, lane = tid&31;
    int wm = (warp>>2)*64, wn = (warp&3)*32;
    int g = lane>>2, tg = lane&3;

    int cr = tid>>3, cch = (tid&7)*8;         // copy: row base, col offset (halfs)
    const __nv_bfloat16* Ap = A  + (size_t)(m0+cr)*lda + cch;
    const __nv_bfloat16* Bp = BT + (size_t)(n0+cr)*ldb + cch;

    // ldmatrix per-lane row offsets (halfs)
    int la = lane & 15, lk = (lane>>4)<<3;
    int aoff[MT];
    #pragma unroll
    for (int mt=0; mt<MT; mt++) aoff[mt] = (wm + mt*16 + la)*ALD + lk;
    int boff[2];
    #pragma unroll
    for (int np=0; np<2; np++)
        boff[np] = (wn + np*16 + ((lane>>4)<<3) + (lane&7))*ALD + ((lane&8)?8:0);

    float acc[MT][NTn][4];
    #pragma unroll
    for (int i=0;i<MT;i++)
        #pragma unroll
        for (int j=0;j<NTn;j++)
            #pragma unroll
            for (int r=0;r<4;r++) acc[i][j][r]=0.f;

    auto issue = [&](int k0, int s){
        __nv_bfloat16* As = hsm + s*ASTG;
        __nv_bfloat16* Bs = hsm + 2*ASTG + s*ASTG;
        #pragma unroll
        for (int i=0;i<4;i++)
            cpa16(&As[(cr+32*i)*ALD + cch], Ap + (size_t)(32*i)*lda + k0);
        #pragma unroll
        for (int i=0;i<4;i++)
            cpa16(&Bs[(cr+32*i)*ALD + cch], Bp + (size_t)(32*i)*ldb + k0);
        cp_commit();
    };

    int nk = K/BKg;
    issue(0, 0);
    for (int it=0; it<nk; it++){
        int s = it&1;
        if (it+1 < nk) issue((it+1)*BKg, s^1);
        if (it+1 < nk) cp_wait<1>(); else cp_wait<0>();
        __syncthreads();

        unsigned abase = hbase + (unsigned)(s*ASTG)*2u;
        unsigned bbase = hbase + (unsigned)((2+s)*ASTG)*2u;
        #pragma unroll
        for (int ks=0; ks<BKg/16; ks++){
            int kk0 = ks*16;
            unsigned af[MT][4], bf[NTn][2];
            #pragma unroll
            for (int mt=0; mt<MT; mt++)
                ldsm4(af[mt], abase + (unsigned)(aoff[mt] + kk0)*2u);
            #pragma unroll
            for (int np=0; np<2; np++){
                unsigned tr[4];
                ldsm4(tr, bbase + (unsigned)(boff[np] + kk0)*2u);
                bf[2*np  ][0]=tr[0]; bf[2*np  ][1]=tr[1];
                bf[2*np+1][0]=tr[2]; bf[2*np+1][1]=tr[3];
            }
            #pragma unroll
            for (int mt=0; mt<MT; mt++)
                #pragma unroll
                for (int nt=0; nt<NTn; nt++)
                    mma16bf(acc[mt][nt], af[mt], bf[nt][0], bf[nt][1]);
        }
        __syncthreads();
    }

    #pragma unroll
    for (int mt=0; mt<MT; mt++){
        #pragma unroll
        for (int i=0; i<2; i++){
            int row = m0 + wm + mt*16 + g + i*8;
            #pragma unroll
            for (int nt=0; nt<NTn; nt++){
                int col = n0 + wn + nt*8 + tg*2;
                float v0 = acc[mt][nt][i*2+0];
                float v1 = acc[mt][nt][i*2+1];
                if (bias){ v0 += bias[col]; v1 += bias[col+1]; }
                if (DO_GELU){ v0 = geluf(v0); v1 = geluf(v1); }
                if (Rm){
                    float2 rr = *(const float2*)(Rm + (size_t)row*ldr + col);
                    v0 += rr.x; v1 += rr.y;
                }
                if (OUT_BF16){
                    __nv_bfloat162 w;
                    w.x = __float2bfloat16_rn(v0);
                    w.y = __float2bfloat16_rn(v1);
                    *(__nv_bfloat162*)((__nv_bfloat16*)Cv + (size_t)row*ldc + col) = w;
                }else{
                    *(float2*)((float*)Cv + (size_t)row*ldc + col) = make_float2(v0, v1);
                }
            }
        }
    }
}

// ---------------- host-side launch helper ---------------------------------------
enum GMode { G_F32, G_BF16, G_GELU_BF16 };
static void gemm_run(const __nv_bfloat16*A,int lda, const __nv_bfloat16*BT,int ldb,
                     void*C,int ldc, int M,int N,int K,
                     const float*bias,const float*R,int ldr, GMode mode)
{
    dim3 gr(N/128, M/128, 1);
    switch (mode){
    case G_F32:
        gemm_bf16<false,false><<<gr,256,GEMM_SMEM>>>(A,lda,BT,ldb,C,ldc,M,N,K,bias,R,ldr); break;
    case G_BF16:
        gemm_bf16<false,true ><<<gr,256,GEMM_SMEM>>>(A,lda,BT,ldb,C,ldc,M,N,K,bias,R,ldr); break;
    case G_GELU_BF16:
        gemm_bf16<true ,true ><<<gr,256,GEMM_SMEM>>>(A,lda,BT,ldb,C,ldc,M,N,K,bias,R,ldr); break;
    }
}

extern "C" void kernel_launch(void* const* d_in, const int* in_sizes, int n_in,
                              void* d_out, int out_size)
{
    (void)in_sizes; (void)n_in; (void)out_size;
    const float* x   = (const float*)d_in[0];
    const float* wq  = (const float*)d_in[1];
    const float* wk  = (const float*)d_in[2];
    const float* wv  = (const float*)d_in[3];
    const float* wo  = (const float*)d_in[4];
    const float* bo  = (const float*)d_in[5];
    const float* l1g = (const float*)d_in[6];
    const float* l1b = (const float*)d_in[7];
    const float* l2g = (const float*)d_in[8];
    const float* l2b = (const float*)d_in[9];
    const float* w1  = (const float*)d_in[10];
    const float* b1  = (const float*)d_in[11];
    const float* w2  = (const float*)d_in[12];
    const float* b2  = (const float*)d_in[13];
    float* out = (float*)d_out;

    void* p;
    __nv_bfloat16 *y,*o,*a,*tmid,*twq,*twk,*twv,*two,*tw1,*tw2;
    float *q,*k,*v,*h;
    cudaGetSymbolAddress(&p, gb_y ); y    = (__nv_bfloat16*)p;
    cudaGetSymbolAddress(&p, g_q  ); q    = (float*)p;
    cudaGetSymbolAddress(&p, g_k  ); k    = (float*)p;
    cudaGetSymbolAddress(&p, g_v  ); v    = (float*)p;
    cudaGetSymbolAddress(&p, gb_o ); o    = (__nv_bfloat16*)p;
    cudaGetSymbolAddress(&p, g_h  ); h    = (float*)p;
    cudaGetSymbolAddress(&p, gb_a ); a    = (__nv_bfloat16*)p;
    cudaGetSymbolAddress(&p, gb_t ); tmid = (__nv_bfloat16*)p;
    cudaGetSymbolAddress(&p, gb_wq); twq  = (__nv_bfloat16*)p;
    cudaGetSymbolAddress(&p, gb_wk); twk  = (__nv_bfloat16*)p;
    cudaGetSymbolAddress(&p, gb_wv); twv  = (__nv_bfloat16*)p;
    cudaGetSymbolAddress(&p, gb_wo); two  = (__nv_bfloat16*)p;
    cudaGetSymbolAddress(&p, gb_w1); tw1  = (__nv_bfloat16*)p;
    cudaGetSymbolAddress(&p, gb_w2); tw2  = (__nv_bfloat16*)p;

    cudaFuncSetAttribute((const void*)flash_kernel,
                         cudaFuncAttributeMaxDynamicSharedMemorySize, FLASH_SMEM);
    cudaFuncSetAttribute((const void*)gemm_bf16<false,false>,
                         cudaFuncAttributeMaxDynamicSharedMemorySize, GEMM_SMEM);
    cudaFuncSetAttribute((const void*)gemm_bf16<false,true>,
                         cudaFuncAttributeMaxDynamicSharedMemorySize, GEMM_SMEM);
    cudaFuncSetAttribute((const void*)gemm_bf16<true,true>,
                         cudaFuncAttributeMaxDynamicSharedMemorySize, GEMM_SMEM);

    // weights -> transposed bf16 copies (W^T[n][k])
    {
        dim3 tb(32,8);
        transpose4_kernel<<<dim3(Dd/32,Dd/32,4),tb>>>(
            wq, wk, wv, wo, twq, twk, twv, two);
        transpose_bf16_kernel<<<dim3(Ff/32,Dd/32),tb>>>(w1, tw1, Dd, Ff);
        transpose_bf16_kernel<<<dim3(Dd/32,Ff/32),tb>>>(w2, tw2, Ff, Dd);
    }

    for (int pass=0; pass<2; pass++){
        const float* lnin = pass ? h   : x;
        const float* gg   = pass ? l2g : l1g;
        const float* bbv  = pass ? l2b : l1b;
        ln_kernel<<<NTOK,256>>>(lnin, gg, bbv, y);
        gemm_run(y,Dd, twq,Dd, q,Dd, NTOK,Dd,Dd, nullptr,nullptr,0, G_F32);
        gemm_run(y,Dd, twk,Dd, k,Dd, NTOK,Dd,Dd, nullptr,nullptr,0, G_F32);
        gemm_run(y,Dd, twv,Dd, v,Dd, NTOK,Dd,Dd, nullptr,nullptr,0, G_F32);
        flash_kernel<<<dim3(16,32),256,FLASH_SMEM>>>(q, k, v, o);
        if (pass == 0)
            gemm_run(o,Dd, two,Dd, h,Dd, NTOK,Dd,Dd, bo, x, Dd, G_F32);
        else
            gemm_run(o,Dd, two,Dd, a,Dd, NTOK,Dd,Dd, bo, nullptr,0, G_BF16);
    }
    // FFN: t = gelu(a@w1 + b1) [bf16];  out = t@w2 + b2 + h  [f32]
    gemm_run(a   ,Dd, tw1,Dd, tmid,Ff, NTOK,Ff,Dd, b1, nullptr,0, G_GELU_BF16);
    gemm_run(tmid,Ff, tw2,Ff, out ,Dd, NTOK,Dd,Ff, b2, h, Dd,     G_F32);
}

// round 17
// speedup vs baseline: 1.7148x; 1.0570x over previous
#include <cuda_runtime.h>
#include <cuda_bf16.h>
#include <math.h>

#define Bb   2
#define Ss   2048
#define Dd   1024
#define Hh   16
#define HDd  64
#define Ff   4096
#define NTOK (Bb*Ss)   // 4096

// ---------------- scratch (device globals) --------------------------------------
__device__ __nv_bfloat16 gb_y[NTOK*Dd];         // LN output (bf16)
__device__ __nv_bfloat16 gb_q[NTOK*Dd];         // Q (bf16, flash input)
__device__ __nv_bfloat16 gb_k[NTOK*Dd];         // K (bf16, flash input)
__device__ float g_v [NTOK*Dd];                 // V (f32 pre-rounded tf32)
__device__ __nv_bfloat16 gb_o[NTOK*Dd];         // attention out (bf16)
__device__ float g_h [NTOK*Dd];                 // residual stream (exact f32)
__device__ __nv_bfloat16 gb_a[NTOK*Dd];         // attn-2 proj out (bf16)
__device__ __nv_bfloat16 gb_t[NTOK*Ff];         // FFN mid (bf16)
// bf16 TRANSPOSED weight copies: W^T[n][k]
__device__ __nv_bfloat16 gb_wq[Dd*Dd], gb_wk[Dd*Dd], gb_wv[Dd*Dd], gb_wo[Dd*Dd];
__device__ __nv_bfloat16 gb_w1[Ff*Dd], gb_w2[Dd*Ff];

// ---------------- helpers -------------------------------------------------------
__device__ __forceinline__ unsigned f2tf(float x){
    unsigned u; asm("cvt.rna.tf32.f32 %0, %1;" : "=r"(u) : "f"(x)); return u;
}
__device__ __forceinline__ float rndtf(float x){ return __uint_as_float(f2tf(x)); }
__device__ __forceinline__ float geluf(float x){
    return 0.5f * x * (1.0f + erff(x * 0.70710678118654752f));
}
__device__ __forceinline__ void mma8(float* c, const unsigned* a, unsigned b0, unsigned b1){
    asm volatile(
        "mma.sync.aligned.m16n8k8.row.col.f32.tf32.tf32.f32 "
        "{%0,%1,%2,%3}, {%4,%5,%6,%7}, {%8,%9}, {%0,%1,%2,%3};"
        : "+f"(c[0]), "+f"(c[1]), "+f"(c[2]), "+f"(c[3])
        : "r"(a[0]), "r"(a[1]), "r"(a[2]), "r"(a[3]), "r"(b0), "r"(b1));
}
__device__ __forceinline__ void mma16bf(float* c, const unsigned* a, unsigned b0, unsigned b1){
    asm volatile(
        "mma.sync.aligned.m16n8k16.row.col.f32.bf16.bf16.f32 "
        "{%0,%1,%2,%3}, {%4,%5,%6,%7}, {%8,%9}, {%0,%1,%2,%3};"
        : "+f"(c[0]), "+f"(c[1]), "+f"(c[2]), "+f"(c[3])
        : "r"(a[0]), "r"(a[1]), "r"(a[2]), "r"(a[3]), "r"(b0), "r"(b1));
}
__device__ __forceinline__ void ldsm4(unsigned* r, unsigned saddr){
    asm volatile("ldmatrix.sync.aligned.m8n8.x4.shared.b16 {%0,%1,%2,%3}, [%4];"
        : "=r"(r[0]), "=r"(r[1]), "=r"(r[2]), "=r"(r[3]) : "r"(saddr));
}
__device__ __forceinline__ void cpa16(void* dst, const void* src){
    unsigned d = (unsigned)__cvta_generic_to_shared(dst);
    asm volatile("cp.async.cg.shared.global [%0], [%1], 16;" :: "r"(d), "l"(src));
}
__device__ __forceinline__ void cp_commit(){ asm volatile("cp.async.commit_group;"); }
template<int N> __device__ __forceinline__ void cp_wait(){
    asm volatile("cp.async.wait_group %0;" :: "n"(N));
}

// ---------------- batched weight transpose: 4x (f32 [1024][1024] -> bf16 W^T) ----
__global__ void transpose4_kernel(const float* s0, const float* s1,
                                  const float* s2, const float* s3,
                                  __nv_bfloat16* d0, __nv_bfloat16* d1,
                                  __nv_bfloat16* d2, __nv_bfloat16* d3)
{
    __shared__ float tile[32][33];
    const float* in; __nv_bfloat16* out;
    switch (blockIdx.z){
        case 0: in=s0; out=d0; break;
        case 1: in=s1; out=d1; break;
        case 2: in=s2; out=d2; break;
        default: in=s3; out=d3; break;
    }
    int k0 = blockIdx.y*32, n0 = blockIdx.x*32;
    int tx = threadIdx.x, ty = threadIdx.y;
    #pragma unroll
    for (int j=0;j<4;j++)
        tile[ty+8*j][tx] = in[(size_t)(k0+ty+8*j)*Dd + n0 + tx];
    __syncthreads();
    #pragma unroll
    for (int j=0;j<4;j++)
        out[(size_t)(n0+ty+8*j)*Dd + k0 + tx] = __float2bfloat16_rn(tile[tx][ty+8*j]);
}

// ---------------- generic transpose-convert: f32 [K][N] -> bf16 [N][K] -----------
__global__ void transpose_bf16_kernel(const float* __restrict__ in,
                                      __nv_bfloat16* __restrict__ out,
                                      int K, int N)
{
    __shared__ float tile[32][33];
    int k0 = blockIdx.y*32, n0 = blockIdx.x*32;
    int tx = threadIdx.x, ty = threadIdx.y;
    #pragma unroll
    for (int j=0;j<4;j++)
        tile[ty+8*j][tx] = in[(size_t)(k0+ty+8*j)*N + n0 + tx];
    __syncthreads();
    #pragma unroll
    for (int j=0;j<4;j++)
        out[(size_t)(n0+ty+8*j)*K + k0 + tx] = __float2bfloat16_rn(tile[tx][ty+8*j]);
}

// ---------------- LayerNorm (bf16 output) ---------------------------------------
__global__ void ln_kernel(const float* __restrict__ x,
                          const float* __restrict__ gam,
                          const float* __restrict__ bet,
                          __nv_bfloat16* __restrict__ y)
{
    __shared__ float rs[2][8];
    int row = blockIdx.x, t = threadIdx.x;
    float4 v = ((const float4*)(x + (size_t)row*Dd))[t];
    float s = v.x+v.y+v.z+v.w;
    float q = v.x*v.x+v.y*v.y+v.z*v.z+v.w*v.w;
    #pragma unroll
    for (int o=16;o;o>>=1){ s += __shfl_xor_sync(0xffffffffu,s,o);
                            q += __shfl_xor_sync(0xffffffffu,q,o); }
    if ((t&31)==0){ rs[0][t>>5]=s; rs[1][t>>5]=q; }
    __syncthreads();
    float S=0.f,Q=0.f;
    #pragma unroll
    for (int i=0;i<8;i++){ S+=rs[0][i]; Q+=rs[1][i]; }
    float mu = S*(1.0f/Dd);
    float var = Q*(1.0f/Dd) - mu*mu;
    float rstd = rsqrtf(var + 1e-5f);
    float4 g4 = ((const float4*)gam)[t];
    float4 b4 = ((const float4*)bet)[t];
    __nv_bfloat162 p0, p1;
    p0.x = __float2bfloat16_rn((v.x-mu)*rstd*g4.x + b4.x);
    p0.y = __float2bfloat16_rn((v.y-mu)*rstd*g4.y + b4.y);
    p1.x = __float2bfloat16_rn((v.z-mu)*rstd*g4.z + b4.z);
    p1.y = __float2bfloat16_rn((v.w-mu)*rstd*g4.w + b4.w);
    __nv_bfloat162* yp = (__nv_bfloat162*)(y + (size_t)row*Dd + t*4);
    yp[0] = p0; yp[1] = p1;
}

// ---------------- flash attention (bf16 QK^T, tf32 PV, online softmax) ----------
// Q,K arrive bf16 (producer-rounded); V arrives f32 pre-rounded to tf32.
// QK fragments use the round-8-proven dense-GEMM a/b mappings (K[key][d] == BT[n][k]).
#define QKB_LD 72                      // halfs per Q/K smem row (144B, CF)
#define VS_LD  72                      // floats per V smem row
#define PS_LD  132
#define FLASH_SMEM ((128*QKB_LD*2)*2 + (128*VS_LD + 128*PS_LD)*4)

__global__ __launch_bounds__(256,1)
void flash_kernel(const __nv_bfloat16* __restrict__ Q,
                  const __nv_bfloat16* __restrict__ K,
                  const float* __restrict__ V, __nv_bfloat16* __restrict__ O)
{
    extern __shared__ float sm[];
    __nv_bfloat16* Qs = (__nv_bfloat16*)sm;            // [128][72] halfs
    __nv_bfloat16* Ks = Qs + 128*QKB_LD;               // [128][72] halfs
    float* Vs = (float*)(Ks + 128*QKB_LD);             // [128][72] floats
    float* Ps = Vs + 128*VS_LD;                        // [128][132] floats

    int qt = 15 - blockIdx.x;
    int z = blockIdx.y, zb = z >> 4, zh = z & 15;
    const __nv_bfloat16* Qp = Q + (size_t)zb*Ss*Dd + zh*HDd;
    const __nv_bfloat16* Kp = K + (size_t)zb*Ss*Dd + zh*HDd;
    const float*         Vp = V + (size_t)zb*Ss*Dd + zh*HDd;
    __nv_bfloat16* Op = O + (size_t)zb*Ss*Dd + zh*HDd;

    int tid = threadIdx.x, warp = tid>>5, lane = tid&31;
    int g = lane>>2, tg = lane&3;
    int q0 = qt*128;

    // load Q tile (raw bf16, uint4 = 8 halfs): 1024 chunks / 256 thr = 4 each
    #pragma unroll
    for (int i=0;i<4;i++){
        int idx = tid + i*256;
        int r = idx>>3, c8 = idx&7;
        *(uint4*)&Qs[r*QKB_LD + c8*8] = *(const uint4*)(Qp + (size_t)(q0+r)*Dd + c8*8);
    }
    __syncthreads();

    // Q a-fragments (m16n8k16 layout, same as dense GEMM): kc = 0..3
    unsigned qf[4][4];
    int pr0 = warp*16 + g;
    #pragma unroll
    for (int kc=0;kc<4;kc++){
        const __nv_bfloat16* ap = Qs + pr0*QKB_LD + kc*16 + 2*tg;
        qf[kc][0] = *(const unsigned*)(ap);
        qf[kc][1] = *(const unsigned*)(ap + 8*QKB_LD);
        qf[kc][2] = *(const unsigned*)(ap + 8);
        qf[kc][3] = *(const unsigned*)(ap + 8*QKB_LD + 8);
    }

    float oa[8][4];
    #pragma unroll
    for (int i=0;i<8;i++){ oa[i][0]=0.f;oa[i][1]=0.f;oa[i][2]=0.f;oa[i][3]=0.f; }
    float m0=-1e30f, m1=-1e30f, l0=0.f, l1=0.f;
    int grow0 = q0 + pr0, grow1 = grow0 + 8;

    int kt0 = (qt==15) ? 0 : qt;
    for (int kt=kt0; kt<16; kt++){
        __syncthreads();
        // K tile: raw bf16 copy (4 uint4/thread); V tile: raw float4 (8/thread)
        #pragma unroll
        for (int i=0;i<4;i++){
            int idx = tid + i*256;
            int r = idx>>3, c8 = idx&7;
            *(uint4*)&Ks[r*QKB_LD + c8*8] =
                *(const uint4*)(Kp + (size_t)(kt*128+r)*Dd + c8*8);
        }
        #pragma unroll
        for (int i=0;i<8;i++){
            int idx = tid + i*256;
            int r = idx>>4, c4 = idx&15;
            *(float4*)&Vs[r*VS_LD + c4*4] =
                *(const float4*)(Vp + (size_t)(kt*128+r)*Dd + c4*4);
        }
        __syncthreads();

        // S = Q @ K^T : bf16 m16n8k16, 4 ksteps x 16 n-tiles
        float sc[16][4];
        #pragma unroll
        for (int nt=0;nt<16;nt++){ sc[nt][0]=0.f;sc[nt][1]=0.f;sc[nt][2]=0.f;sc[nt][3]=0.f; }
        #pragma unroll
        for (int kc=0;kc<4;kc++){
            #pragma unroll
            for (int nt=0;nt<16;nt++){
                const __nv_bfloat16* bp = Ks + (nt*8+g)*QKB_LD + kc*16 + 2*tg;
                unsigned b0 = *(const unsigned*)(bp);
                unsigned b1 = *(const unsigned*)(bp + 8);
                mma16bf(sc[nt], qf[kc], b0, b1);
            }
        }

        float tm0=-1e30f, tm1=-1e30f;
        #pragma unroll
        for (int nt=0;nt<16;nt++){
            #pragma unroll
            for (int j=0;j<4;j++){
                int gcol = kt*128 + nt*8 + tg*2 + (j&1);
                int grow = (j<2) ? grow0 : grow1;
                float s = (gcol<=grow) ? -1e9f : sc[nt][j]*0.125f;
                sc[nt][j] = s;
                if (j<2) tm0 = fmaxf(tm0,s); else tm1 = fmaxf(tm1,s);
            }
        }
        tm0 = fmaxf(tm0, __shfl_xor_sync(0xffffffffu,tm0,1));
        tm0 = fmaxf(tm0, __shfl_xor_sync(0xffffffffu,tm0,2));
        tm1 = fmaxf(tm1, __shfl_xor_sync(0xffffffffu,tm1,1));
        tm1 = fmaxf(tm1, __shfl_xor_sync(0xffffffffu,tm1,2));
        float mn0 = fmaxf(m0,tm0), mn1 = fmaxf(m1,tm1);
        float sf0 = __expf(m0-mn0), sf1 = __expf(m1-mn1);
        float rs0=0.f, rs1=0.f;
        #pragma unroll
        for (int nt=0;nt<16;nt++){
            sc[nt][0] = __expf(sc[nt][0]-mn0); rs0 += sc[nt][0];
            sc[nt][1] = __expf(sc[nt][1]-mn0); rs0 += sc[nt][1];
            sc[nt][2] = __expf(sc[nt][2]-mn1); rs1 += sc[nt][2];
            sc[nt][3] = __expf(sc[nt][3]-mn1); rs1 += sc[nt][3];
        }
        rs0 += __shfl_xor_sync(0xffffffffu,rs0,1);
        rs0 += __shfl_xor_sync(0xffffffffu,rs0,2);
        rs1 += __shfl_xor_sync(0xffffffffu,rs1,1);
        rs1 += __shfl_xor_sync(0xffffffffu,rs1,2);
        l0 = l0*sf0 + rs0;  l1 = l1*sf1 + rs1;
        m0 = mn0;  m1 = mn1;
        #pragma unroll
        for (int i=0;i<8;i++){
            oa[i][0]*=sf0; oa[i][1]*=sf0; oa[i][2]*=sf1; oa[i][3]*=sf1;
        }

        // P (tf32) -> warp-local smem, then PV in tf32 (unchanged from r8)
        #pragma unroll
        for (int nt=0;nt<16;nt++){
            float2 pa, pb;
            pa.x = rndtf(sc[nt][0]); pa.y = rndtf(sc[nt][1]);
            pb.x = rndtf(sc[nt][2]); pb.y = rndtf(sc[nt][3]);
            *(float2*)&Ps[ pr0   *PS_LD + nt*8 + tg*2] = pa;
            *(float2*)&Ps[(pr0+8)*PS_LD + nt*8 + tg*2] = pb;
        }
        __syncwarp();
        #pragma unroll
        for (int kc2=0;kc2<16;kc2++){
            unsigned pf[4];
            pf[0] = __float_as_uint(Ps[ pr0   *PS_LD + kc2*8+tg  ]);
            pf[1] = __float_as_uint(Ps[(pr0+8)*PS_LD + kc2*8+tg  ]);
            pf[2] = __float_as_uint(Ps[ pr0   *PS_LD + kc2*8+tg+4]);
            pf[3] = __float_as_uint(Ps[(pr0+8)*PS_LD + kc2*8+tg+4]);
            #pragma unroll
            for (int nt2=0;nt2<8;nt2++){
                unsigned b0 = __float_as_uint(Vs[(kc2*8+tg  )*VS_LD + nt2*8+g]);
                unsigned b1 = __float_as_uint(Vs[(kc2*8+tg+4)*VS_LD + nt2*8+g]);
                mma8(oa[nt2], pf, b0, b1);
            }
        }
    }

    float inv0 = 1.f/l0, inv1 = 1.f/l1;
    #pragma unroll
    for (int nt2=0;nt2<8;nt2++){
        __nv_bfloat162 w0, w1;
        w0.x = __float2bfloat16_rn(oa[nt2][0]*inv0);
        w0.y = __float2bfloat16_rn(oa[nt2][1]*inv0);
        w1.x = __float2bfloat16_rn(oa[nt2][2]*inv1);
        w1.y = __float2bfloat16_rn(oa[nt2][3]*inv1);
        *(__nv_bfloat162*)(Op + (size_t)grow0*Dd + nt2*8 + tg*2) = w0;
        *(__nv_bfloat162*)(Op + (size_t)grow1*Dd + nt2*8 + tg*2) = w1;
    }
}

// ---------------- pipelined bf16 GEMM (cp.async + ldmatrix, r14-proven) ----------
#define BKg  64
#define ALD  72
#define ASTG (128*ALD)
#define GEMM_SMEM (4*ASTG*2)          // 73728 bytes

template<bool DO_GELU, bool OUT_BF16, bool ROUND_F32>
__global__ __launch_bounds__(256,2)
void gemm_bf16(const __nv_bfloat16* __restrict__ A, int lda,
               const __nv_bfloat16* __restrict__ BT, int ldb,
               void* __restrict__ Cv, int ldc,
               int M, int N, int K,
               const float* __restrict__ bias,
               const float* __restrict__ Rm, int ldr)
{
    constexpr int MT = 4, NTn = 4;
    extern __shared__ __nv_bfloat16 hsm[];
    unsigned hbase = (unsigned)__cvta_generic_to_shared(hsm);

    int m0 = blockIdx.y*128, n0 = blockIdx.x*128;
    int tid = threadIdx.x, warp = tid>>5, lane = tid&31;
    int wm = (warp>>2)*64, wn = (warp&3)*32;
    int g = lane>>2, tg = lane&3;

    int cr = tid>>3, cch = (tid&7)*8;
    const __nv_bfloat16* Ap = A  + (size_t)(m0+cr)*lda + cch;
    const __nv_bfloat16* Bp = BT + (size_t)(n0+cr)*ldb + cch;

    int la = lane & 15, lk = (lane>>4)<<3;
    int aoff[MT];
    #pragma unroll
    for (int mt=0; mt<MT; mt++) aoff[mt] = (wm + mt*16 + la)*ALD + lk;
    int boff[2];
    #pragma unroll
    for (int np=0; np<2; np++)
        boff[np] = (wn + np*16 + ((lane>>4)<<3) + (lane&7))*ALD + ((lane&8)?8:0);

    float acc[MT][NTn][4];
    #pragma unroll
    for (int i=0;i<MT;i++)
        #pragma unroll
        for (int j=0;j<NTn;j++)
            #pragma unroll
            for (int r=0;r<4;r++) acc[i][j][r]=0.f;

    auto issue = [&](int k0, int s){
        __nv_bfloat16* As = hsm + s*ASTG;
        __nv_bfloat16* Bs = hsm + 2*ASTG + s*ASTG;
        #pragma unroll
        for (int i=0;i<4;i++)
            cpa16(&As[(cr+32*i)*ALD + cch], Ap + (size_t)(32*i)*lda + k0);
        #pragma unroll
        for (int i=0;i<4;i++)
            cpa16(&Bs[(cr+32*i)*ALD + cch], Bp + (size_t)(32*i)*ldb + k0);
        cp_commit();
    };

    int nk = K/BKg;
    issue(0, 0);
    for (int it=0; it<nk; it++){
        int s = it&1;
        if (it+1 < nk) issue((it+1)*BKg, s^1);
        if (it+1 < nk) cp_wait<1>(); else cp_wait<0>();
        __syncthreads();

        unsigned abase = hbase + (unsigned)(s*ASTG)*2u;
        unsigned bbase = hbase + (unsigned)((2+s)*ASTG)*2u;
        #pragma unroll
        for (int ks=0; ks<BKg/16; ks++){
            int kk0 = ks*16;
            unsigned af[MT][4], bf[NTn][2];
            #pragma unroll
            for (int mt=0; mt<MT; mt++)
                ldsm4(af[mt], abase + (unsigned)(aoff[mt] + kk0)*2u);
            #pragma unroll
            for (int np=0; np<2; np++){
                unsigned tr[4];
                ldsm4(tr, bbase + (unsigned)(boff[np] + kk0)*2u);
                bf[2*np  ][0]=tr[0]; bf[2*np  ][1]=tr[1];
                bf[2*np+1][0]=tr[2]; bf[2*np+1][1]=tr[3];
            }
            #pragma unroll
            for (int mt=0; mt<MT; mt++)
                #pragma unroll
                for (int nt=0; nt<NTn; nt++)
                    mma16bf(acc[mt][nt], af[mt], bf[nt][0], bf[nt][1]);
        }
        __syncthreads();
    }

    #pragma unroll
    for (int mt=0; mt<MT; mt++){
        #pragma unroll
        for (int i=0; i<2; i++){
            int row = m0 + wm + mt*16 + g + i*8;
            #pragma unroll
            for (int nt=0; nt<NTn; nt++){
                int col = n0 + wn + nt*8 + tg*2;
                float v0 = acc[mt][nt][i*2+0];
                float v1 = acc[mt][nt][i*2+1];
                if (bias){ v0 += bias[col]; v1 += bias[col+1]; }
                if (DO_GELU){ v0 = geluf(v0); v1 = geluf(v1); }
                if (Rm){
                    float2 rr = *(const float2*)(Rm + (size_t)row*ldr + col);
                    v0 += rr.x; v1 += rr.y;
                }
                if (OUT_BF16){
                    __nv_bfloat162 w;
                    w.x = __float2bfloat16_rn(v0);
                    w.y = __float2bfloat16_rn(v1);
                    *(__nv_bfloat162*)((__nv_bfloat16*)Cv + (size_t)row*ldc + col) = w;
                }else{
                    if (ROUND_F32){ v0 = rndtf(v0); v1 = rndtf(v1); }
                    *(float2*)((float*)Cv + (size_t)row*ldc + col) = make_float2(v0, v1);
                }
            }
        }
    }
}

// ---------------- host-side launch helper ---------------------------------------
enum GMode { G_F32, G_F32R, G_BF16, G_GELU_BF16 };
static void gemm_run(const __nv_bfloat16*A,int lda, const __nv_bfloat16*BT,int ldb,
                     void*C,int ldc, int M,int N,int K,
                     const float*bias,const float*R,int ldr, GMode mode)
{
    dim3 gr(N/128, M/128, 1);
    switch (mode){
    case G_F32:
        gemm_bf16<false,false,false><<<gr,256,GEMM_SMEM>>>(A,lda,BT,ldb,C,ldc,M,N,K,bias,R,ldr); break;
    case G_F32R:
        gemm_bf16<false,false,true ><<<gr,256,GEMM_SMEM>>>(A,lda,BT,ldb,C,ldc,M,N,K,bias,R,ldr); break;
    case G_BF16:
        gemm_bf16<false,true ,false><<<gr,256,GEMM_SMEM>>>(A,lda,BT,ldb,C,ldc,M,N,K,bias,R,ldr); break;
    case G_GELU_BF16:
        gemm_bf16<true ,true ,false><<<gr,256,GEMM_SMEM>>>(A,lda,BT,ldb,C,ldc,M,N,K,bias,R,ldr); break;
    }
}

extern "C" void kernel_launch(void* const* d_in, const int* in_sizes, int n_in,
                              void* d_out, int out_size)
{
    (void)in_sizes; (void)n_in; (void)out_size;
    const float* x   = (const float*)d_in[0];
    const float* wq  = (const float*)d_in[1];
    const float* wk  = (const float*)d_in[2];
    const float* wv  = (const float*)d_in[3];
    const float* wo  = (const float*)d_in[4];
    const float* bo  = (const float*)d_in[5];
    const float* l1g = (const float*)d_in[6];
    const float* l1b = (const float*)d_in[7];
    const float* l2g = (const float*)d_in[8];
    const float* l2b = (const float*)d_in[9];
    const float* w1  = (const float*)d_in[10];
    const float* b1  = (const float*)d_in[11];
    const float* w2  = (const float*)d_in[12];
    const float* b2  = (const float*)d_in[13];
    float* out = (float*)d_out;

    void* p;
    __nv_bfloat16 *y,*q,*k,*o,*a,*tmid,*twq,*twk,*twv,*two,*tw1,*tw2;
    float *v,*h;
    cudaGetSymbolAddress(&p, gb_y ); y    = (__nv_bfloat16*)p;
    cudaGetSymbolAddress(&p, gb_q ); q    = (__nv_bfloat16*)p;
    cudaGetSymbolAddress(&p, gb_k ); k    = (__nv_bfloat16*)p;
    cudaGetSymbolAddress(&p, g_v  ); v    = (float*)p;
    cudaGetSymbolAddress(&p, gb_o ); o    = (__nv_bfloat16*)p;
    cudaGetSymbolAddress(&p, g_h  ); h    = (float*)p;
    cudaGetSymbolAddress(&p, gb_a ); a    = (__nv_bfloat16*)p;
    cudaGetSymbolAddress(&p, gb_t ); tmid = (__nv_bfloat16*)p;
    cudaGetSymbolAddress(&p, gb_wq); twq  = (__nv_bfloat16*)p;
    cudaGetSymbolAddress(&p, gb_wk); twk  = (__nv_bfloat16*)p;
    cudaGetSymbolAddress(&p, gb_wv); twv  = (__nv_bfloat16*)p;
    cudaGetSymbolAddress(&p, gb_wo); two  = (__nv_bfloat16*)p;
    cudaGetSymbolAddress(&p, gb_w1); tw1  = (__nv_bfloat16*)p;
    cudaGetSymbolAddress(&p, gb_w2); tw2  = (__nv_bfloat16*)p;

    cudaFuncSetAttribute((const void*)flash_kernel,
                         cudaFuncAttributeMaxDynamicSharedMemorySize, FLASH_SMEM);
    cudaFuncSetAttribute((const void*)gemm_bf16<false,false,false>,
                         cudaFuncAttributeMaxDynamicSharedMemorySize, GEMM_SMEM);
    cudaFuncSetAttribute((const void*)gemm_bf16<false,false,true>,
                         cudaFuncAttributeMaxDynamicSharedMemorySize, GEMM_SMEM);
    cudaFuncSetAttribute((const void*)gemm_bf16<false,true,false>,
                         cudaFuncAttributeMaxDynamicSharedMemorySize, GEMM_SMEM);
    cudaFuncSetAttribute((const void*)gemm_bf16<true,true,false>,
                         cudaFuncAttributeMaxDynamicSharedMemorySize, GEMM_SMEM);

    // weights -> transposed bf16 copies (W^T[n][k])
    {
        dim3 tb(32,8);
        transpose4_kernel<<<dim3(Dd/32,Dd/32,4),tb>>>(
            wq, wk, wv, wo, twq, twk, twv, two);
        transpose_bf16_kernel<<<dim3(Ff/32,Dd/32),tb>>>(w1, tw1, Dd, Ff);
        transpose_bf16_kernel<<<dim3(Dd/32,Ff/32),tb>>>(w2, tw2, Ff, Dd);
    }

    for (int pass=0; pass<2; pass++){
        const float* lnin = pass ? h   : x;
        const float* gg   = pass ? l2g : l1g;
        const float* bbv  = pass ? l2b : l1b;
        ln_kernel<<<NTOK,256>>>(lnin, gg, bbv, y);
        gemm_run(y,Dd, twq,Dd, q,Dd, NTOK,Dd,Dd, nullptr,nullptr,0, G_BF16);
        gemm_run(y,Dd, twk,Dd, k,Dd, NTOK,Dd,Dd, nullptr,nullptr,0, G_BF16);
        gemm_run(y,Dd, twv,Dd, v,Dd, NTOK,Dd,Dd, nullptr,nullptr,0, G_F32R);
        flash_kernel<<<dim3(16,32),256,FLASH_SMEM>>>(q, k, v, o);
        if (pass == 0)
            gemm_run(o,Dd, two,Dd, h,Dd, NTOK,Dd,Dd, bo, x, Dd, G_F32);
        else
            gemm_run(o,Dd, two,Dd, a,Dd, NTOK,Dd,Dd, bo, nullptr,0, G_BF16);
    }
    // FFN: t = gelu(a@w1 + b1) [bf16];  out = t@w2 + b2 + h  [f32]
    gemm_run(a   ,Dd, tw1,Dd, tmid,Ff, NTOK,Ff,Dd, b1, nullptr,0, G_GELU_BF16);
    gemm_run(tmid,Ff, tw2,Ff, out ,Dd, NTOK,Dd,Ff, b2, h, Dd,     G_F32);
}